// round 16
// baseline (speedup 1.0000x reference)
#include <cuda_runtime.h>
#include <cuda_fp16.h>
#include <math.h>
#include <stdint.h>

#define TT 16
#define CCH 64
#define HHH 48
#define WWI 48
#define HWSZ 2304
#define THWSZ 36864
#define WW2 24
#define SS 576
#define RCC 4
#define NCC 8    // channel chunks of 8 in k_offp

// ---------------- mma.sync / ldmatrix / cp.async helpers ----------------
__device__ __forceinline__ uint32_t smem_to_u32(const void* p) {
    uint32_t a;
    asm("{ .reg .u64 tmp; cvta.to.shared.u64 tmp, %1; cvt.u32.u64 %0, tmp; }"
        : "=r"(a) : "l"(p));
    return a;
}
#define LDSM_X4(r0, r1, r2, r3, addr) \
    asm volatile("ldmatrix.sync.aligned.m8n8.x4.shared.b16 {%0,%1,%2,%3}, [%4];" \
        : "=r"(r0), "=r"(r1), "=r"(r2), "=r"(r3) : "r"(addr))
#define MMA_F16(d, a, b) \
    asm volatile("mma.sync.aligned.m16n8k16.row.col.f32.f16.f16.f32 " \
        "{%0,%1,%2,%3}, {%4,%5,%6,%7}, {%8,%9}, {%0,%1,%2,%3};" \
        : "+f"((d)[0]), "+f"((d)[1]), "+f"((d)[2]), "+f"((d)[3]) \
        : "r"((a)[0]), "r"((a)[1]), "r"((a)[2]), "r"((a)[3]), "r"((b)[0]), "r"((b)[1]))
#define TANH_APPROX(d, a) \
    asm("tanh.approx.f32 %0, %1;" : "=f"(d) : "f"(a))
#define CP_A16(dst, src) \
    asm volatile("cp.async.ca.shared.global [%0], [%1], 16;" :: "r"(dst), "l"(src))
#define CP_COMMIT() asm volatile("cp.async.commit_group;" ::: "memory")
#define CP_WAIT_1() asm volatile("cp.async.wait_group 1;" ::: "memory")
#define CP_WAIT_0() asm volatile("cp.async.wait_group 0;" ::: "memory")

// smem tile geometry: fp16 rows padded to 72 elems (144 B)
#define SA 144
#define A_TILE_B (128 * SA)   // 18432
#define B_TILE_B (64 * SA)    // 9216
#define STG 68
#define SM0_TOT (128 * STG * 4)                           // 34816 (k_x2m)
#define SM1_TOT (A_TILE_B + 2 * B_TILE_B)                 // 36864 (gemm1: A + 2x B buf)
#define SM2_TOT (A_TILE_B + 4 * B_TILE_B)                 // 55296 (gemm2: A + 2x (B1+B2))

// ---------------- scratch (device globals; no allocations) ----------------
static __device__ float g_x2[CCH * THWSZ];            // [c][t][h][w]
static __device__ float g_offp[NCC][2 * TT * 2 * SS];
static __device__ float g_off[2 * TT * 2 * SS];
static __device__ __align__(16) unsigned short g_xt_hi[THWSZ * CCH];  // fp16 [t][hw][c]
static __device__ __align__(16) unsigned short pb_sc_hi[2][TT * SS * CCH]; // fp16 [t][s][c]
static __device__ __align__(16) unsigned short pb_cs_hi[2][TT * CCH * SS]; // fp16 [t][c][s]
static __device__ float g_mean[2][TT * HWSZ];
static __device__ float g_maxv[2][TT * HWSZ];
static __device__ float g_varv[2][TT * HWSZ];
static __device__ float g_yv[2][TT * HWSZ];
static __device__ float g_featb[2][TT * HWSZ * CCH]; // [branch][t][hw][c]
static __device__ float g_xd[RCC * THWSZ];
static __device__ float g_agg[RCC * THWSZ];

__device__ __forceinline__ float sigm(float v) { return 1.0f / (1.0f + __expf(-v)); }

__device__ __forceinline__ unsigned short f16_of(float v) {
    __half h = __float2half_rn(v);
    return *(unsigned short*)&h;
}

// ---------------- x transpose + fp16 convert -----------------------------------
__global__ void __launch_bounds__(256) k_xt(const float* __restrict__ x) {
    int idx = blockIdx.x * 256 + threadIdx.x;
    if (idx >= THWSZ) return;
    unsigned short* dh = &g_xt_hi[(size_t)idx * 64];
#pragma unroll 8
    for (int c = 0; c < CCH; c++) {
        dh[c] = f16_of(x[c * THWSZ + idx]);
    }
}

// ---------------- x2 = w_dc2 @ x via fp16 MMA ------------------------------------
__global__ void __launch_bounds__(256, 3) k_x2m(const float* __restrict__ w) {
    extern __shared__ __align__(16) char sm[];
    char* A_hi = sm;                 // xt [128 pos x 64 c]
    char* B_hi = sm + A_TILE_B;      // w16 [64 o x 64 c]
    int tid = threadIdx.x;
    int pos0 = blockIdx.x * 128;

    {
        const uint4* sh = (const uint4*)&g_xt_hi[(size_t)pos0 * 64];
#pragma unroll
        for (int v = 0; v < 4; v++) {
            int i = v * 256 + tid;
            int row = i >> 3, j = i & 7;
            *(uint4*)(A_hi + row * SA + j * 16) = sh[i];
        }
#pragma unroll
        for (int v = 0; v < 16; v++) {
            int i = v * 256 + tid;
            int o = i >> 6, c = i & 63;
            *(unsigned short*)(B_hi + o * SA + c * 2) = f16_of(w[i]);
        }
    }
    __syncthreads();

    int wid = tid >> 5, lane = tid & 31;
    int wm = (wid & 3) * 32;   // pos
    int wn = (wid >> 2) * 32;  // o
    uint32_t ah_u = smem_to_u32(A_hi);
    uint32_t bh_u = smem_to_u32(B_hi);
    int arow = lane & 15;
    int akoff = (lane >> 4) * 16;
    int brow = (lane & 7) + ((lane & 16) ? 8 : 0);
    int bkoff = ((lane >> 3) & 1) * 16;

    float d[2][4][4] = {};
#pragma unroll
    for (int ks = 0; ks < 4; ks++) {
        int kb = ks * 32;
        uint32_t Ah[2][4], Bh[4][2];
#pragma unroll
        for (int mt = 0; mt < 2; mt++) {
            uint32_t off = (uint32_t)((wm + mt * 16 + arow) * SA + kb + akoff);
            LDSM_X4(Ah[mt][0], Ah[mt][1], Ah[mt][2], Ah[mt][3], ah_u + off);
        }
#pragma unroll
        for (int np = 0; np < 2; np++) {
            uint32_t off = (uint32_t)((wn + np * 16 + brow) * SA + kb + bkoff);
            uint32_t r0, r1, r2, r3;
            LDSM_X4(r0, r1, r2, r3, bh_u + off);
            Bh[np * 2][0] = r0; Bh[np * 2][1] = r1;
            Bh[np * 2 + 1][0] = r2; Bh[np * 2 + 1][1] = r3;
        }
#pragma unroll
        for (int mt = 0; mt < 2; mt++)
#pragma unroll
            for (int nt = 0; nt < 4; nt++)
                MMA_F16(d[mt][nt], Ah[mt], Bh[nt]);
    }

    __syncthreads();
    float* stage = (float*)sm;
#pragma unroll
    for (int mt = 0; mt < 2; mt++)
#pragma unroll
        for (int nt = 0; nt < 4; nt++)
#pragma unroll
            for (int r = 0; r < 4; r++) {
                int m = wm + mt * 16 + (lane >> 2) + ((r >> 1) & 1) * 8;
                int n = wn + nt * 8 + (lane & 3) * 2 + (r & 1);
                stage[m * STG + n] = d[mt][nt][r];
            }
    __syncthreads();
    int o = tid >> 2;
    int pg = (tid & 3) * 32;
    float* dst = &g_x2[(size_t)o * THWSZ + pos0 + pg];
#pragma unroll
    for (int q = 0; q < 8; q++) {
        float4 v;
        v.x = stage[(pg + q * 4 + 0) * STG + o];
        v.y = stage[(pg + q * 4 + 1) * STG + o];
        v.z = stage[(pg + q * 4 + 2) * STG + o];
        v.w = stage[(pg + q * 4 + 3) * STG + o];
        *(float4*)&dst[q * 4] = v;
    }
}

// ------- offset conv partials (8 channels, both o per thread) + reduce ----------
__global__ void __launch_bounds__(256) k_offp(const float* __restrict__ x,
                      const float* __restrict__ wl, const float* __restrict__ wr) {
    int idx = blockIdx.x * 256 + threadIdx.x;  // NCC*2*TT*SS = 147456
    int s = idx % SS;
    int t = (idx / SS) & 15;
    int branch = (idx / (SS * TT)) & 1;
    int cc = idx / (SS * TT * 2);
    int i = s / WW2, j = s % WW2;
    int tsrc = (branch == 0) ? min(t + 1, TT - 1) : max(t - 1, 0);
    const float* wofs = (branch == 0) ? wl : wr;
    float acc0 = 0.0f, acc1 = 0.0f;
#pragma unroll
    for (int u = 0; u < 8; u++) {
        int c = cc * 8 + u;
        const float* xp = x + c * THWSZ + t * HWSZ;
        const float* x2p = g_x2 + c * THWSZ + tsrc * HWSZ;
        const float* wp0 = wofs + c * 9;
        const float* wp1 = wofs + (CCH + c) * 9;
#pragma unroll
        for (int ki = 0; ki < 3; ki++) {
            int h = 2 * i - 1 + ki;
            if (h < 0 || h >= HHH) continue;
#pragma unroll
            for (int kj = 0; kj < 3; kj++) {
                int w = 2 * j - 1 + kj;
                if (w < 0 || w >= WWI) continue;
                float v = xp[h * WWI + w] + x2p[h * WWI + w];
                acc0 = fmaf(v, wp0[ki * 3 + kj], acc0);
                acc1 = fmaf(v, wp1[ki * 3 + kj], acc1);
            }
        }
    }
    g_offp[cc][((branch * TT + t) * 2 + 0) * SS + s] = acc0;
    g_offp[cc][((branch * TT + t) * 2 + 1) * SS + s] = acc1;
}

__global__ void k_offred(const float* __restrict__ bl, const float* __restrict__ br_) {
    int i = blockIdx.x * 256 + threadIdx.x;
    if (i >= 2 * TT * 2 * SS) return;
    int branch = i / (TT * 2 * SS);
    int o = (i / SS) & 1;
    float acc = (branch == 0) ? bl[o] : br_[o];
#pragma unroll
    for (int cc = 0; cc < NCC; cc++) acc += g_offp[cc][i];
    g_off[i] = acc;
}

// ------- bilinear grid-sample -> fp16 parts ------------------------------------
__global__ void __launch_bounds__(256) k_sample() {
    int idx = blockIdx.x * 256 + threadIdx.x;
    int s = idx % SS;
    int c4 = (idx / SS) & 15;
    int t = (idx / (SS * 16)) & 15;
    int branch = idx / (SS * 16 * 16);
    int i = s / WW2, j = s % WW2;
    float off0 = g_off[((branch * TT + t) * 2 + 0) * SS + s];
    float off1 = g_off[((branch * TT + t) * 2 + 1) * SS + s];
    float v0 = 2.0f * (float)j + off0;
    float v1 = 2.0f * (float)i + off1;
    float gh = 2.0f * v0 / 23.0f - 1.0f;
    float gw = 2.0f * v1 / 23.0f - 1.0f;
    float xs = ((gh + 1.0f) * 48.0f - 1.0f) * 0.5f;
    float ys = ((gw + 1.0f) * 48.0f - 1.0f) * 0.5f;
    float x0f = floorf(xs), y0f = floorf(ys);
    int x0 = (int)x0f, y0 = (int)y0f;
    float fx = xs - x0f, fy = ys - y0f;
    float wgt[4] = {(1.0f - fx) * (1.0f - fy), fx * (1.0f - fy),
                    (1.0f - fx) * fy, fx * fy};
    int xi[4] = {x0, x0 + 1, x0, x0 + 1};
    int yi[4] = {y0, y0, y0 + 1, y0 + 1};
    float wv[4];
    int id[4];
#pragma unroll
    for (int k = 0; k < 4; k++) {
        bool valid = (xi[k] >= 0) && (xi[k] < WWI) && (yi[k] >= 0) && (yi[k] < HHH);
        wv[k] = valid ? wgt[k] : 0.0f;
        int cy = min(max(yi[k], 0), HHH - 1);
        int cx = min(max(xi[k], 0), WWI - 1);
        id[k] = cy * WWI + cx;
    }
    int tsrc = (branch == 0) ? min(t + 1, TT - 1) : max(t - 1, 0);
#pragma unroll
    for (int u = 0; u < 4; u++) {
        int c = c4 * 4 + u;
        const float* img = g_x2 + c * THWSZ + tsrc * HWSZ;
        float val = wv[0] * img[id[0]] + wv[1] * img[id[1]] +
                    wv[2] * img[id[2]] + wv[3] * img[id[3]];
        unsigned short hs = f16_of(val);
        pb_sc_hi[branch][(t * SS + s) * CCH + c] = hs;
        pb_cs_hi[branch][(t * CCH + c) * SS + s] = hs;
    }
}

// ------- GEMM1-stats: single-pass fp16, cp.async double-buffered B --------------
__global__ void __launch_bounds__(256, 3) k_gemm1_stats() {
    extern __shared__ __align__(16) char sm[];
    char* A_hi = sm;
    uint32_t a_u = smem_to_u32(A_hi);
    uint32_t b_u[2] = {a_u + A_TILE_B, a_u + A_TILE_B + B_TILE_B};
    float* red = (float*)(sm + A_TILE_B);
    int tid = threadIdx.x;
    int t = blockIdx.y, hw0 = blockIdx.x * 128, branch = blockIdx.z;

    // async A tile
    {
        const char* src = (const char*)&g_xt_hi[(size_t)(t * HWSZ + hw0) * 64];
#pragma unroll
        for (int v = 0; v < 4; v++) {
            int i = v * 256 + tid;
            int row = i >> 3, j = i & 7;
            CP_A16(a_u + row * SA + j * 16, src + i * 16);
        }
    }
    // async B chunk 0
    {
        const char* src = (const char*)&pb_sc_hi[branch][(size_t)(t * SS) * 64];
#pragma unroll
        for (int v = 0; v < 2; v++) {
            int i = v * 256 + tid;
            int row = i >> 3, j = i & 7;
            CP_A16(b_u[0] + row * SA + j * 16, src + i * 16);
        }
    }
    CP_COMMIT();

    int wid = tid >> 5, lane = tid & 31;
    int wm = (wid & 3) * 32;
    int wn = (wid >> 2) * 32;
    int arow = lane & 15;
    int akoff = (lane >> 4) * 16;
    int brow = (lane & 7) + ((lane & 16) ? 8 : 0);
    int bkoff = ((lane >> 3) & 1) * 16;

    float s_sum[2][2] = {}, s_sq[2][2] = {};
    float s_mx[2][2] = {{-3.4e38f, -3.4e38f}, {-3.4e38f, -3.4e38f}};
    int buf = 0;

    for (int kc = 0; kc < 9; kc++) {
        if (kc < 8) {
            const char* src = (const char*)&pb_sc_hi[branch][(size_t)(t * SS + (kc + 1) * 64) * 64];
#pragma unroll
            for (int v = 0; v < 2; v++) {
                int i = v * 256 + tid;
                int row = i >> 3, j = i & 7;
                CP_A16(b_u[buf ^ 1] + row * SA + j * 16, src + i * 16);
            }
            CP_COMMIT();
            CP_WAIT_1();
        } else {
            CP_WAIT_0();
        }
        __syncthreads();

        uint32_t bh_u = b_u[buf];
        float d[2][4][4] = {};
#pragma unroll
        for (int ks = 0; ks < 4; ks++) {
            int kb = ks * 32;
            uint32_t Ah[2][4], Bh[4][2];
#pragma unroll
            for (int mt = 0; mt < 2; mt++) {
                uint32_t off = (uint32_t)((wm + mt * 16 + arow) * SA + kb + akoff);
                LDSM_X4(Ah[mt][0], Ah[mt][1], Ah[mt][2], Ah[mt][3], a_u + off);
            }
#pragma unroll
            for (int np = 0; np < 2; np++) {
                uint32_t off = (uint32_t)((wn + np * 16 + brow) * SA + kb + bkoff);
                uint32_t r0, r1, r2, r3;
                LDSM_X4(r0, r1, r2, r3, bh_u + off);
                Bh[np * 2][0] = r0; Bh[np * 2][1] = r1;
                Bh[np * 2 + 1][0] = r2; Bh[np * 2 + 1][1] = r3;
            }
#pragma unroll
            for (int mt = 0; mt < 2; mt++)
#pragma unroll
                for (int nt = 0; nt < 4; nt++)
                    MMA_F16(d[mt][nt], Ah[mt], Bh[nt]);
        }
#pragma unroll
        for (int mt = 0; mt < 2; mt++)
#pragma unroll
            for (int nt = 0; nt < 4; nt++)
#pragma unroll
                for (int r = 0; r < 4; r++) {
                    int rh = (r >> 1) & 1;
                    float v = d[mt][nt][r];
                    s_sum[mt][rh] += v;
                    s_sq[mt][rh] = fmaf(v, v, s_sq[mt][rh]);
                    s_mx[mt][rh] = fmaxf(s_mx[mt][rh], v);
                }
        __syncthreads();
        buf ^= 1;
    }

#pragma unroll
    for (int mt = 0; mt < 2; mt++)
#pragma unroll
        for (int rh = 0; rh < 2; rh++) {
            s_sum[mt][rh] += __shfl_xor_sync(0xFFFFFFFFu, s_sum[mt][rh], 1);
            s_sum[mt][rh] += __shfl_xor_sync(0xFFFFFFFFu, s_sum[mt][rh], 2);
            s_sq[mt][rh] += __shfl_xor_sync(0xFFFFFFFFu, s_sq[mt][rh], 1);
            s_sq[mt][rh] += __shfl_xor_sync(0xFFFFFFFFu, s_sq[mt][rh], 2);
            s_mx[mt][rh] = fmaxf(s_mx[mt][rh], __shfl_xor_sync(0xFFFFFFFFu, s_mx[mt][rh], 1));
            s_mx[mt][rh] = fmaxf(s_mx[mt][rh], __shfl_xor_sync(0xFFFFFFFFu, s_mx[mt][rh], 2));
        }
    if ((lane & 3) == 0) {
        int nw = wid >> 2;
#pragma unroll
        for (int mt = 0; mt < 2; mt++)
#pragma unroll
            for (int rh = 0; rh < 2; rh++) {
                int m = wm + mt * 16 + (lane >> 2) + 8 * rh;
                float* p = &red[(nw * 128 + m) * 3];
                p[0] = s_sum[mt][rh];
                p[1] = s_sq[mt][rh];
                p[2] = s_mx[mt][rh];
            }
    }
    __syncthreads();
    if (tid < 128) {
        int m = tid;
        const float* p0 = &red[m * 3];
        const float* p1 = &red[(128 + m) * 3];
        float sum = p0[0] + p1[0];
        float sq = p0[1] + p1[1];
        float mx = fmaxf(p0[2], p1[2]);
        int o = t * HWSZ + hw0 + m;
        g_mean[branch][o] = sum / 576.0f;
        g_maxv[branch][o] = mx;
        g_varv[branch][o] = (sq - sum * sum / 576.0f) / 575.0f;
    }
}

// ---------------- attention gate (both branches) --------------------------------
__global__ void k_y(const float* __restrict__ w1, const float* __restrict__ w2) {
    int gidx = blockIdx.x * 256 + threadIdx.x;
    if (gidx >= 2 * TT * HWSZ) return;
    int branch = gidx / (TT * HWSZ);
    int idx = gidx % (TT * HWSZ);
    int t = idx / HWSZ;
    int hw = idx % HWSZ;
    int h = hw / WWI, w = hw % WWI;
    float acc = 0.0f;
#pragma unroll
    for (int dh = 0; dh < 3; dh++) {
        int hh = h + dh - 1;
        if (hh < 0 || hh >= HHH) continue;
#pragma unroll
        for (int dw = 0; dw < 3; dw++) {
            int ww = w + dw - 1;
            if (ww < 0 || ww >= WWI) continue;
            int p = t * HWSZ + hh * WWI + ww;
            acc = fmaf(w1[(0 * 3 + dh) * 3 + dw], g_mean[branch][p], acc);
            acc = fmaf(w1[(3 + dh) * 3 + dw], g_maxv[branch][p], acc);
            acc = fmaf(w2[dh * 3 + dw], g_varv[branch][p], acc);
        }
    }
    g_yv[branch][idx] = sigm(acc);
}

// ------- fused GEMM2: register-forwarded gate, cp.async double-buffered B -------
__global__ void __launch_bounds__(256, 2) k_gemm2f(const float* __restrict__ w2s) {
    extern __shared__ __align__(16) char sm[];
    char* A1_hi = sm;
    uint32_t a1_u = smem_to_u32(A1_hi);
    // per buffer b: B1 at a1_u + A + b*2*B_TILE_B ; B2 at +B_TILE_B further
    uint32_t b1_u[2] = {a1_u + A_TILE_B, a1_u + A_TILE_B + 2 * B_TILE_B};
    uint32_t b2_u[2] = {b1_u[0] + B_TILE_B, b1_u[1] + B_TILE_B};
    int tid = threadIdx.x;
    int t = blockIdx.y, hw0 = blockIdx.x * 128, branch = blockIdx.z;

    // async A tile + chunk 0 B tiles
    {
        const char* srcA = (const char*)&g_xt_hi[(size_t)(t * HWSZ + hw0) * 64];
#pragma unroll
        for (int v = 0; v < 4; v++) {
            int i = v * 256 + tid;
            int row = i >> 3, j = i & 7;
            CP_A16(a1_u + row * SA + j * 16, srcA + i * 16);
        }
        const char* srcB1 = (const char*)&pb_sc_hi[branch][(size_t)(t * SS) * 64];
#pragma unroll
        for (int v = 0; v < 2; v++) {
            int i = v * 256 + tid;
            int row = i >> 3, j = i & 7;
            CP_A16(b1_u[0] + row * SA + j * 16, srcB1 + i * 16);
        }
#pragma unroll
        for (int v = 0; v < 2; v++) {
            int i = v * 256 + tid;
            int row = i >> 3, j = i & 7;
            size_t src = (size_t)(t * CCH + row) * SS + j * 8;
            CP_A16(b2_u[0] + row * SA + j * 16, (const char*)&pb_cs_hi[branch][src]);
        }
    }
    CP_COMMIT();

    int wid = tid >> 5, lane = tid & 31;
    int wm = wid * 16;
    int arow = lane & 15;
    int akoff = (lane >> 4) * 16;
    int brow = (lane & 7) + ((lane & 16) ? 8 : 0);
    int bkoff = ((lane >> 3) & 1) * 16;

    float yv0 = 0.5f * g_yv[branch][t * HWSZ + hw0 + wm + (lane >> 2)];
    float yv1 = 0.5f * g_yv[branch][t * HWSZ + hw0 + wm + (lane >> 2) + 8];

    float d2[8][4];
#pragma unroll
    for (int nt = 0; nt < 8; nt++)
#pragma unroll
        for (int r = 0; r < 4; r++) d2[nt][r] = 0.0f;

    int buf = 0;
    for (int kc = 0; kc < 9; kc++) {
        if (kc < 8) {
            const char* srcB1 = (const char*)&pb_sc_hi[branch][(size_t)(t * SS + (kc + 1) * 64) * 64];
#pragma unroll
            for (int v = 0; v < 2; v++) {
                int i = v * 256 + tid;
                int row = i >> 3, j = i & 7;
                CP_A16(b1_u[buf ^ 1] + row * SA + j * 16, srcB1 + i * 16);
            }
#pragma unroll
            for (int v = 0; v < 2; v++) {
                int i = v * 256 + tid;
                int row = i >> 3, j = i & 7;
                size_t src = (size_t)(t * CCH + row) * SS + (kc + 1) * 64 + j * 8;
                CP_A16(b2_u[buf ^ 1] + row * SA + j * 16, (const char*)&pb_cs_hi[branch][src]);
            }
            CP_COMMIT();
            CP_WAIT_1();
        } else {
            CP_WAIT_0();
        }
        __syncthreads();

        // mma1: d1 = A1 x B1^T
        float d1[8][4];
#pragma unroll
        for (int nt = 0; nt < 8; nt++)
#pragma unroll
            for (int r = 0; r < 4; r++) d1[nt][r] = 0.0f;
#pragma unroll
        for (int ks = 0; ks < 4; ks++) {
            int kb = ks * 32;
            uint32_t Ah[4], Bh[8][2];
            LDSM_X4(Ah[0], Ah[1], Ah[2], Ah[3],
                    a1_u + (uint32_t)((wm + arow) * SA + kb + akoff));
#pragma unroll
            for (int np = 0; np < 4; np++) {
                uint32_t r0, r1, r2, r3;
                LDSM_X4(r0, r1, r2, r3,
                        b1_u[buf] + (uint32_t)((np * 16 + brow) * SA + kb + bkoff));
                Bh[np * 2][0] = r0; Bh[np * 2][1] = r1;
                Bh[np * 2 + 1][0] = r2; Bh[np * 2 + 1][1] = r3;
            }
#pragma unroll
            for (int nt = 0; nt < 8; nt++)
                MMA_F16(d1[nt], Ah, Bh[nt]);
        }

        // gate in registers -> A2 fragments -> mma2
#pragma unroll
        for (int ks2 = 0; ks2 < 4; ks2++) {
            uint32_t Af[4];
            {
                float t0, t1;
                TANH_APPROX(t0, yv0 * d1[2 * ks2][0]);
                TANH_APPROX(t1, yv0 * d1[2 * ks2][1]);
                Af[0] = (uint32_t)f16_of(0.5f * t0) | ((uint32_t)f16_of(0.5f * t1) << 16);
                TANH_APPROX(t0, yv1 * d1[2 * ks2][2]);
                TANH_APPROX(t1, yv1 * d1[2 * ks2][3]);
                Af[1] = (uint32_t)f16_of(0.5f * t0) | ((uint32_t)f16_of(0.5f * t1) << 16);
                TANH_APPROX(t0, yv0 * d1[2 * ks2 + 1][0]);
                TANH_APPROX(t1, yv0 * d1[2 * ks2 + 1][1]);
                Af[2] = (uint32_t)f16_of(0.5f * t0) | ((uint32_t)f16_of(0.5f * t1) << 16);
                TANH_APPROX(t0, yv1 * d1[2 * ks2 + 1][2]);
                TANH_APPROX(t1, yv1 * d1[2 * ks2 + 1][3]);
                Af[3] = (uint32_t)f16_of(0.5f * t0) | ((uint32_t)f16_of(0.5f * t1) << 16);
            }
            uint32_t Bh2[8][2];
#pragma unroll
            for (int np = 0; np < 4; np++) {
                uint32_t r0, r1, r2, r3;
                LDSM_X4(r0, r1, r2, r3,
                        b2_u[buf] + (uint32_t)((np * 16 + brow) * SA + ks2 * 32 + bkoff));
                Bh2[np * 2][0] = r0; Bh2[np * 2][1] = r1;
                Bh2[np * 2 + 1][0] = r2; Bh2[np * 2 + 1][1] = r3;
            }
#pragma unroll
            for (int nt = 0; nt < 8; nt++)
                MMA_F16(d2[nt], Af, Bh2[nt]);
        }
        __syncthreads();
        buf ^= 1;
    }

    // stage + scaled store
    float* stage = (float*)sm;
#pragma unroll
    for (int nt = 0; nt < 8; nt++)
#pragma unroll
        for (int r = 0; r < 4; r++) {
            int m = wm + (lane >> 2) + ((r >> 1) & 1) * 8;
            int n = nt * 8 + (lane & 3) * 2 + (r & 1);
            stage[m * STG + n] = d2[nt][r];
        }
    __syncthreads();
    float wscale = w2s[branch];
    int row = tid >> 1, half = tid & 1;
    const float* srow = &stage[row * STG + half * 32];
    float* dst = &g_featb[branch][((size_t)t * HWSZ + hw0 + row) * CCH + half * 32];
#pragma unroll
    for (int q = 0; q < 8; q++) {
        float4 b = *(const float4*)&srow[q * 4];
        float4 o4 = make_float4(b.x * wscale, b.y * wscale, b.z * wscale, b.w * wscale);
        *(float4*)&dst[q * 4] = o4;
    }
}

// ---------------- xd = w_down @ x (one thread per pos, 4 outputs) ---------------
__global__ void k_xd(const float* __restrict__ x, const float* __restrict__ wd) {
    int pos = blockIdx.x * blockDim.x + threadIdx.x;
    if (pos >= THWSZ) return;
    float a0 = 0.0f, a1 = 0.0f, a2 = 0.0f, a3 = 0.0f;
    for (int c = 0; c < CCH; c++) {
        float v = x[c * THWSZ + pos];
        a0 = fmaf(wd[c], v, a0);
        a1 = fmaf(wd[CCH + c], v, a1);
        a2 = fmaf(wd[2 * CCH + c], v, a2);
        a3 = fmaf(wd[3 * CCH + c], v, a3);
    }
    g_xd[pos] = a0;
    g_xd[THWSZ + pos] = a1;
    g_xd[2 * THWSZ + pos] = a2;
    g_xd[3 * THWSZ + pos] = a3;
}

// ---------------- 3x depthwise 3D convs ------------------------------------------
__global__ void k_agg(const float* __restrict__ w1, const float* __restrict__ b1,
                      const float* __restrict__ w2, const float* __restrict__ b2,
                      const float* __restrict__ w3, const float* __restrict__ b3,
                      const float* __restrict__ wts) {
    int idx = blockIdx.x * blockDim.x + threadIdx.x;
    if (idx >= RCC * THWSZ) return;
    int r = idx / THWSZ;
    int rem = idx % THWSZ;
    int t = rem / HWSZ;
    int hw = rem % HWSZ;
    int h = hw / WWI, w = hw % WWI;
    const float* xb = g_xd + r * THWSZ;
    const float* ws_[3] = {w1, w2, w3};
    const float* bs_[3] = {b1, b2, b3};
    float total = 0.0f;
#pragma unroll
    for (int m = 0; m < 3; m++) {
        int d = m + 1;
        float cs = bs_[m][r];
        const float* wp = ws_[m] + r * 81;
        for (int kt = 0; kt < 9; kt++) {
            int ti = t + kt - 4;
            if (ti < 0 || ti >= TT) continue;
#pragma unroll
            for (int kh = 0; kh < 3; kh++) {
                int hi = h + (kh - 1) * d;
                if (hi < 0 || hi >= HHH) continue;
#pragma unroll
                for (int kw = 0; kw < 3; kw++) {
                    int wi = w + (kw - 1) * d;
                    if (wi < 0 || wi >= WWI) continue;
                    cs = fmaf(xb[ti * HWSZ + hi * WWI + wi], wp[(kt * 3 + kh) * 3 + kw], cs);
                }
            }
        }
        total = fmaf(wts[m], cs, total);
    }
    g_agg[idx] = total;
}

// ---------------- final ----------------------------------------------------------
__global__ void k_final(float* __restrict__ out, const float* __restrict__ wback) {
    int pos = blockIdx.x * 256 + threadIdx.x;
    if (pos >= THWSZ) return;
    float ag0 = g_agg[pos];
    float ag1 = g_agg[THWSZ + pos];
    float ag2 = g_agg[2 * THWSZ + pos];
    float ag3 = g_agg[3 * THWSZ + pos];
    const float4* f0 = (const float4*)&g_featb[0][(size_t)pos * CCH];
    const float4* f1 = (const float4*)&g_featb[1][(size_t)pos * CCH];
#pragma unroll
    for (int c4 = 0; c4 < 16; c4++) {
        float4 a = f0[c4];
        float4 b = f1[c4];
        float fv[4] = {a.x + b.x, a.y + b.y, a.z + b.z, a.w + b.w};
#pragma unroll
        for (int u = 0; u < 4; u++) {
            int c = c4 * 4 + u;
            float z = wback[c * 4 + 0] * ag0 + wback[c * 4 + 1] * ag1 +
                      wback[c * 4 + 2] * ag2 + wback[c * 4 + 3] * ag3;
            out[c * THWSZ + pos] = fv[u] * (sigm(z) - 0.5f);
        }
    }
}

extern "C" void kernel_launch(void* const* d_in, const int* in_sizes, int n_in,
                              void* d_out, int out_size) {
    const float* x       = (const float*)d_in[0];
    const float* w_dc2   = (const float*)d_in[1];
    const float* w_ofs_l = (const float*)d_in[2];
    const float* b_ofs_l = (const float*)d_in[3];
    const float* w_ofs_r = (const float*)d_in[4];
    const float* b_ofs_r = (const float*)d_in[5];
    const float* ca_w1   = (const float*)d_in[6];
    const float* ca_w2   = (const float*)d_in[7];
    const float* w_down  = (const float*)d_in[8];
    const float* sa1_w   = (const float*)d_in[9];
    const float* sa1_b   = (const float*)d_in[10];
    const float* sa2_w   = (const float*)d_in[11];
    const float* sa2_b   = (const float*)d_in[12];
    const float* sa3_w   = (const float*)d_in[13];
    const float* sa3_b   = (const float*)d_in[14];
    const float* weights = (const float*)d_in[15];
    const float* weights2= (const float*)d_in[16];
    const float* w_back  = (const float*)d_in[17];
    float* out = (float*)d_out;

    static cudaStream_t s2 = 0;
    static cudaEvent_t evFork = 0, evAGG = 0;
    if (s2 == 0) {
        cudaStreamCreateWithFlags(&s2, cudaStreamNonBlocking);
        cudaEventCreateWithFlags(&evFork, cudaEventDisableTiming);
        cudaEventCreateWithFlags(&evAGG, cudaEventDisableTiming);
        cudaFuncSetAttribute(k_x2m, cudaFuncAttributeMaxDynamicSharedMemorySize, SM0_TOT);
        cudaFuncSetAttribute(k_gemm1_stats, cudaFuncAttributeMaxDynamicSharedMemorySize, SM1_TOT);
        cudaFuncSetAttribute(k_gemm2f, cudaFuncAttributeMaxDynamicSharedMemorySize, SM2_TOT);
    }

    // fork side stream (xd/agg depend only on x)
    cudaEventRecord(evFork, 0);
    cudaStreamWaitEvent(s2, evFork, 0);
    k_xd<<<(THWSZ + 255) / 256, 256, 0, s2>>>(x, w_down);
    k_agg<<<(RCC * THWSZ + 255) / 256, 256, 0, s2>>>(sa1_w, sa1_b, sa2_w, sa2_b, sa3_w, sa3_b, weights);
    cudaEventRecord(evAGG, s2);

    // main stream
    k_xt<<<(THWSZ + 255) / 256, 256>>>(x);
    k_x2m<<<THWSZ / 128, 256, SM0_TOT>>>(w_dc2);
    k_offp<<<(NCC * 2 * TT * SS) / 256, 256>>>(x, w_ofs_l, w_ofs_r);
    k_offred<<<(2 * TT * 2 * SS + 255) / 256, 256>>>(b_ofs_l, b_ofs_r);
    k_sample<<<(2 * TT * 16 * SS) / 256, 256>>>();

    dim3 gg(HWSZ / 128, TT, 2);
    k_gemm1_stats<<<gg, 256, SM1_TOT>>>();
    k_y<<<(2 * TT * HWSZ + 255) / 256, 256>>>(ca_w1, ca_w2);
    k_gemm2f<<<gg, 256, SM2_TOT>>>(weights2);

    cudaStreamWaitEvent(0, evAGG, 0);  // k_final needs g_agg
    k_final<<<(THWSZ + 255) / 256, 256>>>(out, w_back);
}

// round 17
// speedup vs baseline: 1.0479x; 1.0479x over previous
#include <cuda_runtime.h>
#include <cuda_fp16.h>
#include <math.h>
#include <stdint.h>

#define TT 16
#define CCH 64
#define HHH 48
#define WWI 48
#define HWSZ 2304
#define THWSZ 36864
#define WW2 24
#define SS 576
#define RCC 4
#define NCC 16   // channel chunks of 4 in k_offp

// ---------------- mma.sync / ldmatrix helpers ----------------
__device__ __forceinline__ uint32_t smem_to_u32(const void* p) {
    uint32_t a;
    asm("{ .reg .u64 tmp; cvta.to.shared.u64 tmp, %1; cvt.u32.u64 %0, tmp; }"
        : "=r"(a) : "l"(p));
    return a;
}
#define LDSM_X4(r0, r1, r2, r3, addr) \
    asm volatile("ldmatrix.sync.aligned.m8n8.x4.shared.b16 {%0,%1,%2,%3}, [%4];" \
        : "=r"(r0), "=r"(r1), "=r"(r2), "=r"(r3) : "r"(addr))
#define MMA_F16(d, a, b) \
    asm volatile("mma.sync.aligned.m16n8k16.row.col.f32.f16.f16.f32 " \
        "{%0,%1,%2,%3}, {%4,%5,%6,%7}, {%8,%9}, {%0,%1,%2,%3};" \
        : "+f"((d)[0]), "+f"((d)[1]), "+f"((d)[2]), "+f"((d)[3]) \
        : "r"((a)[0]), "r"((a)[1]), "r"((a)[2]), "r"((a)[3]), "r"((b)[0]), "r"((b)[1]))
#define TANH_APPROX(d, a) \
    asm("tanh.approx.f32 %0, %1;" : "=f"(d) : "f"(a))

// smem tile geometry: fp16 rows padded to 72 elems (144 B)
#define SA 144
#define A_TILE_B (128 * SA)   // 18432
#define B_TILE_B (64 * SA)    // 9216
#define STG 68
#define SM0_TOT (128 * STG * 4)                           // 34816 (k_xtx2: tiles < stage)
#define SM1_TOT (A_TILE_B + B_TILE_B)                     // 27648
#define SM2_TOT (A_TILE_B + 2 * B_TILE_B)                 // 36864

// ---------------- scratch (device globals; no allocations) ----------------
static __device__ float g_x2[CCH * THWSZ];            // [c][t][h][w]
static __device__ float g_offp[NCC][2 * TT * 2 * SS];
static __device__ float g_off[2 * TT * 2 * SS];
static __device__ __align__(16) unsigned short g_xt_hi[THWSZ * CCH];  // fp16 [t][hw][c]
static __device__ __align__(16) unsigned short pb_sc_hi[2][TT * SS * CCH]; // fp16 [t][s][c]
static __device__ __align__(16) unsigned short pb_cs_hi[2][TT * CCH * SS]; // fp16 [t][c][s]
static __device__ float g_mean[2][TT * HWSZ];
static __device__ float g_maxv[2][TT * HWSZ];
static __device__ float g_varv[2][TT * HWSZ];
static __device__ float g_yv[2][TT * HWSZ];
static __device__ float g_featb[2][TT * HWSZ * CCH]; // [branch][t][hw][c]
static __device__ float g_xd[RCC * THWSZ];
static __device__ float g_agg[RCC * THWSZ];

__device__ __forceinline__ float sigm(float v) { return 1.0f / (1.0f + __expf(-v)); }

__device__ __forceinline__ unsigned short f16_of(float v) {
    __half h = __float2half_rn(v);
    return *(unsigned short*)&h;
}

// ------- fused: xt transpose/convert + x2 = w_dc2 @ x via fp16 MMA ---------------
// block: 128 pos. Loads x coalesced, builds fp16 A tile, writes g_xt_hi coalesced,
// then MMA with w (fp16) and transposed epilogue to g_x2. grid 288.
__global__ void __launch_bounds__(256, 3) k_xtx2(const float* __restrict__ x,
                                                 const float* __restrict__ w) {
    extern __shared__ __align__(16) char sm[];
    char* A_hi = sm;                 // [128 pos x 64 c] fp16, row stride SA
    char* B_hi = sm + A_TILE_B;      // w16 [64 o x 64 c]
    int tid = threadIdx.x;
    int pos0 = blockIdx.x * 128;

    // load x (coalesced per c-row), convert, transpose into A tile
#pragma unroll
    for (int v = 0; v < 16; v++) {
        int i = v * 256 + tid;       // 4096: (cpair, p)
        int p = i & 127, cp = i >> 7;
        float v0 = x[(size_t)(2 * cp) * THWSZ + pos0 + p];
        float v1 = x[(size_t)(2 * cp + 1) * THWSZ + pos0 + p];
        uint32_t pk = (uint32_t)f16_of(v0) | ((uint32_t)f16_of(v1) << 16);
        *(uint32_t*)(A_hi + p * SA + cp * 4) = pk;
    }
    // w -> B tile (fp16)
#pragma unroll
    for (int v = 0; v < 16; v++) {
        int i = v * 256 + tid;
        int o = i >> 6, c = i & 63;
        *(unsigned short*)(B_hi + o * SA + c * 2) = f16_of(w[i]);
    }
    __syncthreads();

    // coalesced write of g_xt_hi from the A tile
    {
        uint4* dst = (uint4*)&g_xt_hi[(size_t)pos0 * 64];
#pragma unroll
        for (int v = 0; v < 4; v++) {
            int i = v * 256 + tid;
            int row = i >> 3, j = i & 7;
            dst[i] = *(uint4*)(A_hi + row * SA + j * 16);
        }
    }

    int wid = tid >> 5, lane = tid & 31;
    int wm = (wid & 3) * 32;   // pos
    int wn = (wid >> 2) * 32;  // o
    uint32_t ah_u = smem_to_u32(A_hi);
    uint32_t bh_u = smem_to_u32(B_hi);
    int arow = lane & 15;
    int akoff = (lane >> 4) * 16;
    int brow = (lane & 7) + ((lane & 16) ? 8 : 0);
    int bkoff = ((lane >> 3) & 1) * 16;

    float d[2][4][4] = {};
#pragma unroll
    for (int ks = 0; ks < 4; ks++) {
        int kb = ks * 32;
        uint32_t Ah[2][4], Bh[4][2];
#pragma unroll
        for (int mt = 0; mt < 2; mt++) {
            uint32_t off = (uint32_t)((wm + mt * 16 + arow) * SA + kb + akoff);
            LDSM_X4(Ah[mt][0], Ah[mt][1], Ah[mt][2], Ah[mt][3], ah_u + off);
        }
#pragma unroll
        for (int np = 0; np < 2; np++) {
            uint32_t off = (uint32_t)((wn + np * 16 + brow) * SA + kb + bkoff);
            uint32_t r0, r1, r2, r3;
            LDSM_X4(r0, r1, r2, r3, bh_u + off);
            Bh[np * 2][0] = r0; Bh[np * 2][1] = r1;
            Bh[np * 2 + 1][0] = r2; Bh[np * 2 + 1][1] = r3;
        }
#pragma unroll
        for (int mt = 0; mt < 2; mt++)
#pragma unroll
            for (int nt = 0; nt < 4; nt++)
                MMA_F16(d[mt][nt], Ah[mt], Bh[nt]);
    }

    // stage D[pos][o] then transposed coalesced write to g_x2[o][pos]
    __syncthreads();
    float* stage = (float*)sm;
#pragma unroll
    for (int mt = 0; mt < 2; mt++)
#pragma unroll
        for (int nt = 0; nt < 4; nt++)
#pragma unroll
            for (int r = 0; r < 4; r++) {
                int m = wm + mt * 16 + (lane >> 2) + ((r >> 1) & 1) * 8;
                int n = wn + nt * 8 + (lane & 3) * 2 + (r & 1);
                stage[m * STG + n] = d[mt][nt][r];
            }
    __syncthreads();
    int o = tid >> 2;
    int pg = (tid & 3) * 32;
    float* dst = &g_x2[(size_t)o * THWSZ + pos0 + pg];
#pragma unroll
    for (int q = 0; q < 8; q++) {
        float4 v;
        v.x = stage[(pg + q * 4 + 0) * STG + o];
        v.y = stage[(pg + q * 4 + 1) * STG + o];
        v.z = stage[(pg + q * 4 + 2) * STG + o];
        v.w = stage[(pg + q * 4 + 3) * STG + o];
        *(float4*)&dst[q * 4] = v;
    }
}

// ------- offset conv partials (both o per thread) + reduce ---------------------
__global__ void __launch_bounds__(256) k_offp(const float* __restrict__ x,
                      const float* __restrict__ wl, const float* __restrict__ wr) {
    int idx = blockIdx.x * 256 + threadIdx.x;  // NCC*2*TT*SS = 294912
    int s = idx % SS;
    int t = (idx / SS) & 15;
    int branch = (idx / (SS * TT)) & 1;
    int cc = idx / (SS * TT * 2);
    int i = s / WW2, j = s % WW2;
    int tsrc = (branch == 0) ? min(t + 1, TT - 1) : max(t - 1, 0);
    const float* wofs = (branch == 0) ? wl : wr;
    float acc0 = 0.0f, acc1 = 0.0f;
#pragma unroll
    for (int u = 0; u < 4; u++) {
        int c = cc * 4 + u;
        const float* xp = x + c * THWSZ + t * HWSZ;
        const float* x2p = g_x2 + c * THWSZ + tsrc * HWSZ;
        const float* wp0 = wofs + c * 9;
        const float* wp1 = wofs + (CCH + c) * 9;
#pragma unroll
        for (int ki = 0; ki < 3; ki++) {
            int h = 2 * i - 1 + ki;
            if (h < 0 || h >= HHH) continue;
#pragma unroll
            for (int kj = 0; kj < 3; kj++) {
                int w = 2 * j - 1 + kj;
                if (w < 0 || w >= WWI) continue;
                float v = xp[h * WWI + w] + x2p[h * WWI + w];
                acc0 = fmaf(v, wp0[ki * 3 + kj], acc0);
                acc1 = fmaf(v, wp1[ki * 3 + kj], acc1);
            }
        }
    }
    g_offp[cc][((branch * TT + t) * 2 + 0) * SS + s] = acc0;
    g_offp[cc][((branch * TT + t) * 2 + 1) * SS + s] = acc1;
}

__global__ void k_offred(const float* __restrict__ bl, const float* __restrict__ br_) {
    int i = blockIdx.x * 256 + threadIdx.x;
    if (i >= 2 * TT * 2 * SS) return;
    int branch = i / (TT * 2 * SS);
    int o = (i / SS) & 1;
    float acc = (branch == 0) ? bl[o] : br_[o];
#pragma unroll
    for (int cc = 0; cc < NCC; cc++) acc += g_offp[cc][i];
    g_off[i] = acc;
}

// ------- bilinear grid-sample -> fp16 parts ------------------------------------
__global__ void __launch_bounds__(256) k_sample() {
    int idx = blockIdx.x * 256 + threadIdx.x;
    int s = idx % SS;
    int c4 = (idx / SS) & 15;
    int t = (idx / (SS * 16)) & 15;
    int branch = idx / (SS * 16 * 16);
    int i = s / WW2, j = s % WW2;
    float off0 = g_off[((branch * TT + t) * 2 + 0) * SS + s];
    float off1 = g_off[((branch * TT + t) * 2 + 1) * SS + s];
    float v0 = 2.0f * (float)j + off0;
    float v1 = 2.0f * (float)i + off1;
    float gh = 2.0f * v0 / 23.0f - 1.0f;
    float gw = 2.0f * v1 / 23.0f - 1.0f;
    float xs = ((gh + 1.0f) * 48.0f - 1.0f) * 0.5f;
    float ys = ((gw + 1.0f) * 48.0f - 1.0f) * 0.5f;
    float x0f = floorf(xs), y0f = floorf(ys);
    int x0 = (int)x0f, y0 = (int)y0f;
    float fx = xs - x0f, fy = ys - y0f;
    float wgt[4] = {(1.0f - fx) * (1.0f - fy), fx * (1.0f - fy),
                    (1.0f - fx) * fy, fx * fy};
    int xi[4] = {x0, x0 + 1, x0, x0 + 1};
    int yi[4] = {y0, y0, y0 + 1, y0 + 1};
    float wv[4];
    int id[4];
#pragma unroll
    for (int k = 0; k < 4; k++) {
        bool valid = (xi[k] >= 0) && (xi[k] < WWI) && (yi[k] >= 0) && (yi[k] < HHH);
        wv[k] = valid ? wgt[k] : 0.0f;
        int cy = min(max(yi[k], 0), HHH - 1);
        int cx = min(max(xi[k], 0), WWI - 1);
        id[k] = cy * WWI + cx;
    }
    int tsrc = (branch == 0) ? min(t + 1, TT - 1) : max(t - 1, 0);
#pragma unroll
    for (int u = 0; u < 4; u++) {
        int c = c4 * 4 + u;
        const float* img = g_x2 + c * THWSZ + tsrc * HWSZ;
        float val = wv[0] * img[id[0]] + wv[1] * img[id[1]] +
                    wv[2] * img[id[2]] + wv[3] * img[id[3]];
        unsigned short hs = f16_of(val);
        pb_sc_hi[branch][(t * SS + s) * CCH + c] = hs;
        pb_cs_hi[branch][(t * CCH + c) * SS + s] = hs;
    }
}

// ------- GEMM1-stats: single-pass fp16, both branches ---------------------------
__global__ void __launch_bounds__(256, 3) k_gemm1_stats() {
    extern __shared__ __align__(16) char sm[];
    char* A_hi = sm;
    char* B_hi = sm + A_TILE_B;
    float* red = (float*)(sm + A_TILE_B);
    int tid = threadIdx.x;
    int t = blockIdx.y, hw0 = blockIdx.x * 128, branch = blockIdx.z;

    {
        const uint4* sh = (const uint4*)&g_xt_hi[(size_t)(t * HWSZ + hw0) * 64];
#pragma unroll
        for (int v = 0; v < 4; v++) {
            int i = v * 256 + tid;
            int row = i >> 3, j = i & 7;
            *(uint4*)(A_hi + row * SA + j * 16) = sh[i];
        }
    }

    int wid = tid >> 5, lane = tid & 31;
    int wm = (wid & 3) * 32;
    int wn = (wid >> 2) * 32;
    uint32_t ah_u = smem_to_u32(A_hi);
    uint32_t bh_u = smem_to_u32(B_hi);
    int arow = lane & 15;
    int akoff = (lane >> 4) * 16;
    int brow = (lane & 7) + ((lane & 16) ? 8 : 0);
    int bkoff = ((lane >> 3) & 1) * 16;

    float s_sum[2][2] = {}, s_sq[2][2] = {};
    float s_mx[2][2] = {{-3.4e38f, -3.4e38f}, {-3.4e38f, -3.4e38f}};

    for (int kc = 0; kc < 9; kc++) {
        __syncthreads();
        {
            const uint4* bh = (const uint4*)&pb_sc_hi[branch][(size_t)(t * SS + kc * 64) * 64];
#pragma unroll
            for (int v = 0; v < 2; v++) {
                int i = v * 256 + tid;
                int row = i >> 3, j = i & 7;
                *(uint4*)(B_hi + row * SA + j * 16) = bh[i];
            }
        }
        __syncthreads();

        float d[2][4][4] = {};
#pragma unroll
        for (int ks = 0; ks < 4; ks++) {
            int kb = ks * 32;
            uint32_t Ah[2][4], Bh[4][2];
#pragma unroll
            for (int mt = 0; mt < 2; mt++) {
                uint32_t off = (uint32_t)((wm + mt * 16 + arow) * SA + kb + akoff);
                LDSM_X4(Ah[mt][0], Ah[mt][1], Ah[mt][2], Ah[mt][3], ah_u + off);
            }
#pragma unroll
            for (int np = 0; np < 2; np++) {
                uint32_t off = (uint32_t)((wn + np * 16 + brow) * SA + kb + bkoff);
                uint32_t r0, r1, r2, r3;
                LDSM_X4(r0, r1, r2, r3, bh_u + off);
                Bh[np * 2][0] = r0; Bh[np * 2][1] = r1;
                Bh[np * 2 + 1][0] = r2; Bh[np * 2 + 1][1] = r3;
            }
#pragma unroll
            for (int mt = 0; mt < 2; mt++)
#pragma unroll
                for (int nt = 0; nt < 4; nt++)
                    MMA_F16(d[mt][nt], Ah[mt], Bh[nt]);
        }
#pragma unroll
        for (int mt = 0; mt < 2; mt++)
#pragma unroll
            for (int nt = 0; nt < 4; nt++)
#pragma unroll
                for (int r = 0; r < 4; r++) {
                    int rh = (r >> 1) & 1;
                    float v = d[mt][nt][r];
                    s_sum[mt][rh] += v;
                    s_sq[mt][rh] = fmaf(v, v, s_sq[mt][rh]);
                    s_mx[mt][rh] = fmaxf(s_mx[mt][rh], v);
                }
    }

#pragma unroll
    for (int mt = 0; mt < 2; mt++)
#pragma unroll
        for (int rh = 0; rh < 2; rh++) {
            s_sum[mt][rh] += __shfl_xor_sync(0xFFFFFFFFu, s_sum[mt][rh], 1);
            s_sum[mt][rh] += __shfl_xor_sync(0xFFFFFFFFu, s_sum[mt][rh], 2);
            s_sq[mt][rh] += __shfl_xor_sync(0xFFFFFFFFu, s_sq[mt][rh], 1);
            s_sq[mt][rh] += __shfl_xor_sync(0xFFFFFFFFu, s_sq[mt][rh], 2);
            s_mx[mt][rh] = fmaxf(s_mx[mt][rh], __shfl_xor_sync(0xFFFFFFFFu, s_mx[mt][rh], 1));
            s_mx[mt][rh] = fmaxf(s_mx[mt][rh], __shfl_xor_sync(0xFFFFFFFFu, s_mx[mt][rh], 2));
        }
    __syncthreads();
    if ((lane & 3) == 0) {
        int nw = wid >> 2;
#pragma unroll
        for (int mt = 0; mt < 2; mt++)
#pragma unroll
            for (int rh = 0; rh < 2; rh++) {
                int m = wm + mt * 16 + (lane >> 2) + 8 * rh;
                float* p = &red[(nw * 128 + m) * 3];
                p[0] = s_sum[mt][rh];
                p[1] = s_sq[mt][rh];
                p[2] = s_mx[mt][rh];
            }
    }
    __syncthreads();
    if (tid < 128) {
        int m = tid;
        const float* p0 = &red[m * 3];
        const float* p1 = &red[(128 + m) * 3];
        float sum = p0[0] + p1[0];
        float sq = p0[1] + p1[1];
        float mx = fmaxf(p0[2], p1[2]);
        int o = t * HWSZ + hw0 + m;
        g_mean[branch][o] = sum / 576.0f;
        g_maxv[branch][o] = mx;
        g_varv[branch][o] = (sq - sum * sum / 576.0f) / 575.0f;
    }
}

// ---------------- attention gate (both branches) --------------------------------
__global__ void k_y(const float* __restrict__ w1, const float* __restrict__ w2) {
    int gidx = blockIdx.x * 256 + threadIdx.x;
    if (gidx >= 2 * TT * HWSZ) return;
    int branch = gidx / (TT * HWSZ);
    int idx = gidx % (TT * HWSZ);
    int t = idx / HWSZ;
    int hw = idx % HWSZ;
    int h = hw / WWI, w = hw % WWI;
    float acc = 0.0f;
#pragma unroll
    for (int dh = 0; dh < 3; dh++) {
        int hh = h + dh - 1;
        if (hh < 0 || hh >= HHH) continue;
#pragma unroll
        for (int dw = 0; dw < 3; dw++) {
            int ww = w + dw - 1;
            if (ww < 0 || ww >= WWI) continue;
            int p = t * HWSZ + hh * WWI + ww;
            acc = fmaf(w1[(0 * 3 + dh) * 3 + dw], g_mean[branch][p], acc);
            acc = fmaf(w1[(3 + dh) * 3 + dw], g_maxv[branch][p], acc);
            acc = fmaf(w2[dh * 3 + dw], g_varv[branch][p], acc);
        }
    }
    g_yv[branch][idx] = sigm(acc);
}

// ------- fused GEMM2: register-forwarded gate, 8mx1n warps ----------------------
__global__ void __launch_bounds__(256, 2) k_gemm2f(const float* __restrict__ w2s) {
    extern __shared__ __align__(16) char sm[];
    char* A1_hi = sm;                          // xt [128hw x 64c]
    char* B1_hi = sm + A_TILE_B;               // part_sc [64s x 64c]
    char* B2_hi = sm + A_TILE_B + B_TILE_B;    // part_cs [64c x 64s]
    int tid = threadIdx.x;
    int t = blockIdx.y, hw0 = blockIdx.x * 128, branch = blockIdx.z;

    {
        const uint4* sh = (const uint4*)&g_xt_hi[(size_t)(t * HWSZ + hw0) * 64];
#pragma unroll
        for (int v = 0; v < 4; v++) {
            int i = v * 256 + tid;
            int row = i >> 3, j = i & 7;
            *(uint4*)(A1_hi + row * SA + j * 16) = sh[i];
        }
    }

    int wid = tid >> 5, lane = tid & 31;
    int wm = wid * 16;  // 8 warps x 16 hw-rows each
    uint32_t a1h_u = smem_to_u32(A1_hi);
    uint32_t b1h_u = smem_to_u32(B1_hi);
    uint32_t b2h_u = smem_to_u32(B2_hi);
    int arow = lane & 15;
    int akoff = (lane >> 4) * 16;
    int brow = (lane & 7) + ((lane & 16) ? 8 : 0);
    int bkoff = ((lane >> 3) & 1) * 16;

    float yv0 = 0.5f * g_yv[branch][t * HWSZ + hw0 + wm + (lane >> 2)];
    float yv1 = 0.5f * g_yv[branch][t * HWSZ + hw0 + wm + (lane >> 2) + 8];

    float d2[8][4];
#pragma unroll
    for (int nt = 0; nt < 8; nt++)
#pragma unroll
        for (int r = 0; r < 4; r++) d2[nt][r] = 0.0f;

    for (int kc = 0; kc < 9; kc++) {
        __syncthreads();
        {
            const uint4* bh = (const uint4*)&pb_sc_hi[branch][(size_t)(t * SS + kc * 64) * 64];
#pragma unroll
            for (int v = 0; v < 2; v++) {
                int i = v * 256 + tid;
                int row = i >> 3, j = i & 7;
                *(uint4*)(B1_hi + row * SA + j * 16) = bh[i];
            }
#pragma unroll
            for (int v = 0; v < 2; v++) {
                int i = v * 256 + tid;
                int row = i >> 3, j = i & 7;
                size_t src = (size_t)(t * CCH + row) * SS + kc * 64 + j * 8;
                *(uint4*)(B2_hi + row * SA + j * 16) = *(const uint4*)&pb_cs_hi[branch][src];
            }
        }
        __syncthreads();

        // mma1: d1[8 nt_s][4] = A1(16 hw x 64 c) x B1(64 s x 64 c)^T
        float d1[8][4];
#pragma unroll
        for (int nt = 0; nt < 8; nt++)
#pragma unroll
            for (int r = 0; r < 4; r++) d1[nt][r] = 0.0f;
#pragma unroll
        for (int ks = 0; ks < 4; ks++) {
            int kb = ks * 32;
            uint32_t Ah[4], Bh[8][2];
            LDSM_X4(Ah[0], Ah[1], Ah[2], Ah[3],
                    a1h_u + (uint32_t)((wm + arow) * SA + kb + akoff));
#pragma unroll
            for (int np = 0; np < 4; np++) {
                uint32_t r0, r1, r2, r3;
                LDSM_X4(r0, r1, r2, r3,
                        b1h_u + (uint32_t)((np * 16 + brow) * SA + kb + bkoff));
                Bh[np * 2][0] = r0; Bh[np * 2][1] = r1;
                Bh[np * 2 + 1][0] = r2; Bh[np * 2 + 1][1] = r3;
            }
#pragma unroll
            for (int nt = 0; nt < 8; nt++)
                MMA_F16(d1[nt], Ah, Bh[nt]);
        }

        // gate d1 in registers -> A2 fragments, feed mma2 directly
#pragma unroll
        for (int ks2 = 0; ks2 < 4; ks2++) {
            uint32_t Af[4];
            {
                float t0, t1;
                TANH_APPROX(t0, yv0 * d1[2 * ks2][0]);
                TANH_APPROX(t1, yv0 * d1[2 * ks2][1]);
                Af[0] = (uint32_t)f16_of(0.5f * t0) | ((uint32_t)f16_of(0.5f * t1) << 16);
                TANH_APPROX(t0, yv1 * d1[2 * ks2][2]);
                TANH_APPROX(t1, yv1 * d1[2 * ks2][3]);
                Af[1] = (uint32_t)f16_of(0.5f * t0) | ((uint32_t)f16_of(0.5f * t1) << 16);
                TANH_APPROX(t0, yv0 * d1[2 * ks2 + 1][0]);
                TANH_APPROX(t1, yv0 * d1[2 * ks2 + 1][1]);
                Af[2] = (uint32_t)f16_of(0.5f * t0) | ((uint32_t)f16_of(0.5f * t1) << 16);
                TANH_APPROX(t0, yv1 * d1[2 * ks2 + 1][2]);
                TANH_APPROX(t1, yv1 * d1[2 * ks2 + 1][3]);
                Af[3] = (uint32_t)f16_of(0.5f * t0) | ((uint32_t)f16_of(0.5f * t1) << 16);
            }
            uint32_t Bh2[8][2];
#pragma unroll
            for (int np = 0; np < 4; np++) {
                uint32_t r0, r1, r2, r3;
                LDSM_X4(r0, r1, r2, r3,
                        b2h_u + (uint32_t)((np * 16 + brow) * SA + ks2 * 32 + bkoff));
                Bh2[np * 2][0] = r0; Bh2[np * 2][1] = r1;
                Bh2[np * 2 + 1][0] = r2; Bh2[np * 2 + 1][1] = r3;
            }
#pragma unroll
            for (int nt = 0; nt < 8; nt++)
                MMA_F16(d2[nt], Af, Bh2[nt]);
        }
    }

    // stage + scaled store
    __syncthreads();
    float* stage = (float*)sm;
#pragma unroll
    for (int nt = 0; nt < 8; nt++)
#pragma unroll
        for (int r = 0; r < 4; r++) {
            int m = wm + (lane >> 2) + ((r >> 1) & 1) * 8;
            int n = nt * 8 + (lane & 3) * 2 + (r & 1);
            stage[m * STG + n] = d2[nt][r];
        }
    __syncthreads();
    float wscale = w2s[branch];
    int row = tid >> 1, half = tid & 1;
    const float* srow = &stage[row * STG + half * 32];
    float* dst = &g_featb[branch][((size_t)t * HWSZ + hw0 + row) * CCH + half * 32];
#pragma unroll
    for (int q = 0; q < 8; q++) {
        float4 b = *(const float4*)&srow[q * 4];
        float4 o4 = make_float4(b.x * wscale, b.y * wscale, b.z * wscale, b.w * wscale);
        *(float4*)&dst[q * 4] = o4;
    }
}

// ---------------- xd = w_down @ x (one thread per pos, 4 outputs) ---------------
__global__ void k_xd(const float* __restrict__ x, const float* __restrict__ wd) {
    int pos = blockIdx.x * blockDim.x + threadIdx.x;
    if (pos >= THWSZ) return;
    float a0 = 0.0f, a1 = 0.0f, a2 = 0.0f, a3 = 0.0f;
    for (int c = 0; c < CCH; c++) {
        float v = x[c * THWSZ + pos];
        a0 = fmaf(wd[c], v, a0);
        a1 = fmaf(wd[CCH + c], v, a1);
        a2 = fmaf(wd[2 * CCH + c], v, a2);
        a3 = fmaf(wd[3 * CCH + c], v, a3);
    }
    g_xd[pos] = a0;
    g_xd[THWSZ + pos] = a1;
    g_xd[2 * THWSZ + pos] = a2;
    g_xd[3 * THWSZ + pos] = a3;
}

// ---------------- 3x depthwise 3D convs ------------------------------------------
__global__ void k_agg(const float* __restrict__ w1, const float* __restrict__ b1,
                      const float* __restrict__ w2, const float* __restrict__ b2,
                      const float* __restrict__ w3, const float* __restrict__ b3,
                      const float* __restrict__ wts) {
    int idx = blockIdx.x * blockDim.x + threadIdx.x;
    if (idx >= RCC * THWSZ) return;
    int r = idx / THWSZ;
    int rem = idx % THWSZ;
    int t = rem / HWSZ;
    int hw = rem % HWSZ;
    int h = hw / WWI, w = hw % WWI;
    const float* xb = g_xd + r * THWSZ;
    const float* ws_[3] = {w1, w2, w3};
    const float* bs_[3] = {b1, b2, b3};
    float total = 0.0f;
#pragma unroll
    for (int m = 0; m < 3; m++) {
        int d = m + 1;
        float cs = bs_[m][r];
        const float* wp = ws_[m] + r * 81;
        for (int kt = 0; kt < 9; kt++) {
            int ti = t + kt - 4;
            if (ti < 0 || ti >= TT) continue;
#pragma unroll
            for (int kh = 0; kh < 3; kh++) {
                int hi = h + (kh - 1) * d;
                if (hi < 0 || hi >= HHH) continue;
#pragma unroll
                for (int kw = 0; kw < 3; kw++) {
                    int wi = w + (kw - 1) * d;
                    if (wi < 0 || wi >= WWI) continue;
                    cs = fmaf(xb[ti * HWSZ + hi * WWI + wi], wp[(kt * 3 + kh) * 3 + kw], cs);
                }
            }
        }
        total = fmaf(wts[m], cs, total);
    }
    g_agg[idx] = total;
}

// ---------------- final ----------------------------------------------------------
__global__ void k_final(float* __restrict__ out, const float* __restrict__ wback) {
    int pos = blockIdx.x * 256 + threadIdx.x;
    if (pos >= THWSZ) return;
    float ag0 = g_agg[pos];
    float ag1 = g_agg[THWSZ + pos];
    float ag2 = g_agg[2 * THWSZ + pos];
    float ag3 = g_agg[3 * THWSZ + pos];
    const float4* f0 = (const float4*)&g_featb[0][(size_t)pos * CCH];
    const float4* f1 = (const float4*)&g_featb[1][(size_t)pos * CCH];
#pragma unroll
    for (int c4 = 0; c4 < 16; c4++) {
        float4 a = f0[c4];
        float4 b = f1[c4];
        float fv[4] = {a.x + b.x, a.y + b.y, a.z + b.z, a.w + b.w};
#pragma unroll
        for (int u = 0; u < 4; u++) {
            int c = c4 * 4 + u;
            float z = wback[c * 4 + 0] * ag0 + wback[c * 4 + 1] * ag1 +
                      wback[c * 4 + 2] * ag2 + wback[c * 4 + 3] * ag3;
            out[c * THWSZ + pos] = fv[u] * (sigm(z) - 0.5f);
        }
    }
}

extern "C" void kernel_launch(void* const* d_in, const int* in_sizes, int n_in,
                              void* d_out, int out_size) {
    const float* x       = (const float*)d_in[0];
    const float* w_dc2   = (const float*)d_in[1];
    const float* w_ofs_l = (const float*)d_in[2];
    const float* b_ofs_l = (const float*)d_in[3];
    const float* w_ofs_r = (const float*)d_in[4];
    const float* b_ofs_r = (const float*)d_in[5];
    const float* ca_w1   = (const float*)d_in[6];
    const float* ca_w2   = (const float*)d_in[7];
    const float* w_down  = (const float*)d_in[8];
    const float* sa1_w   = (const float*)d_in[9];
    const float* sa1_b   = (const float*)d_in[10];
    const float* sa2_w   = (const float*)d_in[11];
    const float* sa2_b   = (const float*)d_in[12];
    const float* sa3_w   = (const float*)d_in[13];
    const float* sa3_b   = (const float*)d_in[14];
    const float* weights = (const float*)d_in[15];
    const float* weights2= (const float*)d_in[16];
    const float* w_back  = (const float*)d_in[17];
    float* out = (float*)d_out;

    static cudaStream_t s2 = 0;
    static cudaEvent_t evFork = 0, evAGG = 0;
    if (s2 == 0) {
        cudaStreamCreateWithFlags(&s2, cudaStreamNonBlocking);
        cudaEventCreateWithFlags(&evFork, cudaEventDisableTiming);
        cudaEventCreateWithFlags(&evAGG, cudaEventDisableTiming);
        cudaFuncSetAttribute(k_xtx2, cudaFuncAttributeMaxDynamicSharedMemorySize, SM0_TOT);
        cudaFuncSetAttribute(k_gemm1_stats, cudaFuncAttributeMaxDynamicSharedMemorySize, SM1_TOT);
        cudaFuncSetAttribute(k_gemm2f, cudaFuncAttributeMaxDynamicSharedMemorySize, SM2_TOT);
    }

    // fork side stream (xd/agg depend only on x)
    cudaEventRecord(evFork, 0);
    cudaStreamWaitEvent(s2, evFork, 0);
    k_xd<<<(THWSZ + 255) / 256, 256, 0, s2>>>(x, w_down);
    k_agg<<<(RCC * THWSZ + 255) / 256, 256, 0, s2>>>(sa1_w, sa1_b, sa2_w, sa2_b, sa3_w, sa3_b, weights);
    cudaEventRecord(evAGG, s2);

    // main stream
    k_xtx2<<<THWSZ / 128, 256, SM0_TOT>>>(x, w_dc2);
    k_offp<<<(NCC * 2 * TT * SS) / 256, 256>>>(x, w_ofs_l, w_ofs_r);
    k_offred<<<(2 * TT * 2 * SS + 255) / 256, 256>>>(b_ofs_l, b_ofs_r);
    k_sample<<<(2 * TT * 16 * SS) / 256, 256>>>();

    dim3 gg(HWSZ / 128, TT, 2);
    k_gemm1_stats<<<gg, 256, SM1_TOT>>>();
    k_y<<<(2 * TT * HWSZ + 255) / 256, 256>>>(ca_w1, ca_w2);
    k_gemm2f<<<gg, 256, SM2_TOT>>>(weights2);

    cudaStreamWaitEvent(0, evAGG, 0);  // k_final needs g_agg
    k_final<<<(THWSZ + 255) / 256, 256>>>(out, w_back);
}